// round 10
// baseline (speedup 1.0000x reference)
#include <cuda_runtime.h>
#include <cstdint>

#define NODES   64
#define NINPUT  16
#define NOUT    8
#define NEDGE   256
#define BATCH   8192
#define PASSES  64
#define G       16            // edge slots per chunk (lanes per column)
#define TB      128           // threads per block
#define CPB     8             // columns per block (2 cols per warp)
#define GRIDB   (BATCH / CPB) // 1024 blocks
#define STRIDE  80            // floats per column; 80 = 16 mod 32 -> warp halves
                              // sit at bank offset +16, so dsts distinct mod 16
                              // give ZERO dst bank conflicts warp-wide
#define MAXCH   257           // worst case chunks + wrap chunk

__device__ uint2 g_recs[MAXCH * G + G];
__device__ int   g_nchunks;

// 64-bit inclusive OR-scan across the warp
__device__ __forceinline__ unsigned long long orscan_incl(unsigned long long x,
                                                          int lane) {
    #pragma unroll
    for (int o = 1; o < 32; o <<= 1) {
        unsigned lo = __shfl_up_sync(0xffffffffu, (unsigned)x, o);
        unsigned hi = __shfl_up_sync(0xffffffffu, (unsigned)(x >> 32), o);
        unsigned long long y = ((unsigned long long)hi << 32) | lo;
        if (lane >= o) x |= y;
    }
    return x;
}

__device__ __forceinline__ unsigned long long bcast64(unsigned long long x,
                                                      int srclane) {
    unsigned lo = __shfl_sync(0xffffffffu, (unsigned)x, srclane);
    unsigned hi = __shfl_sync(0xffffffffu, (unsigned)(x >> 32), srclane);
    return ((unsigned long long)hi << 32) | lo;
}

// ---------------------------------------------------------------------------
// Warp-parallel greedy list scheduler (R6 base) with residue-aware acceptance
// ordering. Chunks pack earliest-first (depth preserved). Within a batch, ok
// candidates are accepted in three priority rounds:
//   1) dst residue (d mod 16) new to the chunk  -> conflict-free dst LDS/STS
//   2) src residue (s mod 16) new to the chunk  -> fewer src LDS conflicts
//   3) everything else (backfill keeps fill optimal)
// Dependence rules (proven in R6): RAW via W-footprint on src, WAR via
// R-footprint on dst, in-chunk dst distinctness; WAW across chunks relaxed
// (fp adds commute; reassociation only).
// rec.x = (dst_byte_off << 16) | src_byte_off, rec.y = w * 2*log2(e).
// ---------------------------------------------------------------------------
__global__ void sched_kernel(const float* __restrict__ wght,
                             const int*   __restrict__ src,
                             const int*   __restrict__ dst) {
    __shared__ int   ss[NEDGE], sd[NEDGE];
    __shared__ float sw[NEDGE];
    __shared__ short rlist[NEDGE], tmpl[NEDGE];
    __shared__ unsigned char accf[NEDGE];
    const int lane = threadIdx.x;
    const float K2 = 2.8853900817779268f;  // 2 * log2(e)

    for (int e = lane; e < NEDGE; e += 32) {
        ss[e] = src[e]; sd[e] = dst[e]; sw[e] = wght[e] * K2;
        rlist[e] = (short)e;
    }
    __syncwarp();

    const unsigned ltmask = (1u << lane) - 1u;

    int nrem = NEDGE, nch = 0;
    while (nrem > 0) {
        // clear accept flags for every remaining position (scan may early-exit)
        for (int i = lane; i < nrem; i += 32) accf[i] = 0;
        __syncwarp();

        unsigned long long Wall = 0ull, Rall = 0ull, Wmem = 0ull;
        unsigned Bm = 0u;          // dst residues (mod 16) used by members
        unsigned Sm = 0u;          // src residues (mod 16) used by members
        int members = 0;
        for (int base = 0; base < nrem && members < G; base += 32) {
            const int  idx   = base + lane;
            const bool valid = idx < nrem;
            const int  e = valid ? rlist[idx] : 0;
            const int  s = ss[e], d = sd[e];
            const unsigned long long myW = valid ? (1ull << d) : 0ull;
            const unsigned long long myR = valid ? (1ull << s) : 0ull;
            const unsigned long long iW = orscan_incl(myW, lane);
            const unsigned long long iR = orscan_incl(myR, lane);
            unsigned lo = __shfl_up_sync(0xffffffffu, (unsigned)iW, 1);
            unsigned hi = __shfl_up_sync(0xffffffffu, (unsigned)(iW >> 32), 1);
            const unsigned long long eW =
                (lane == 0) ? 0ull : (((unsigned long long)hi << 32) | lo);
            lo = __shfl_up_sync(0xffffffffu, (unsigned)iR, 1);
            hi = __shfl_up_sync(0xffffffffu, (unsigned)(iR >> 32), 1);
            const unsigned long long eR =
                (lane == 0) ? 0ull : (((unsigned long long)hi << 32) | lo);

            const unsigned long long tWall = Wall | eW;  // excl scan, all W
            const unsigned long long tRall = Rall | eR;  // excl scan, all R
            const bool ok0 = valid &&
                             !((tWall >> s) & 1ull) &&
                             !((tRall >> d) & 1ull) &&
                             !((Wmem  >> d) & 1ull);
            // intra-batch member-dst dedup (keep lowest ok0 lane per dst)
            const unsigned peers = __match_any_sync(0xffffffffu, d);
            const unsigned bal0  = __ballot_sync(0xffffffffu, ok0);
            const bool ok = ok0 && ((peers & bal0 & ltmask) == 0u);

            const unsigned dres = 1u << (d & 15);
            const unsigned sres = 1u << (s & 15);

            // --- round 1: dst residue new to chunk ---
            const unsigned balok  = __ballot_sync(0xffffffffu, ok);
            const unsigned dpeers = __match_any_sync(0xffffffffu, d & 15);
            const bool dfirst = ok && ((dpeers & balok & ltmask) == 0u);
            const bool p1 = dfirst && !(Bm & dres);
            const unsigned bal1 = __ballot_sync(0xffffffffu, p1);
            const int  rank1 = members + __popc(bal1 & ltmask);
            const bool acc1  = p1 && (rank1 < G);
            const int  m1 = members + __popc(__ballot_sync(0xffffffffu, acc1));

            // --- round 2: src residue new to chunk ---
            const bool rem2 = ok && !p1;
            const unsigned balr2  = __ballot_sync(0xffffffffu, rem2);
            const unsigned speers = __match_any_sync(0xffffffffu, s & 15);
            const bool sfirst = rem2 && ((speers & balr2 & ltmask) == 0u);
            const bool p2 = sfirst && !(Sm & sres);
            const unsigned bal2 = __ballot_sync(0xffffffffu, p2);
            const int  rank2 = m1 + __popc(bal2 & ltmask);
            const bool acc2  = p2 && (rank2 < G);
            const int  m2 = m1 + __popc(__ballot_sync(0xffffffffu, acc2));

            // --- round 3: backfill ---
            const bool rest = ok && !p1 && !p2;
            const unsigned bal3 = __ballot_sync(0xffffffffu, rest);
            const int  rank3 = m2 + __popc(bal3 & ltmask);
            const bool acc3  = rest && (rank3 < G);

            const bool accept = acc1 || acc2 || acc3;
            const int  rank   = acc1 ? rank1 : (acc2 ? rank2 : rank3);

            if (accept) {
                uint2 rec;
                rec.x = ((unsigned)(d * 4) << 16) | (unsigned)(s * 4);
                rec.y = __float_as_uint(sw[e]);
                g_recs[nch * G + rank] = rec;
                accf[idx] = 1;
            }
            members = m2 + __popc(__ballot_sync(0xffffffffu, acc3));
            // fold footprints of everything scanned + member residue sets
            Wall |= bcast64(iW, 31);
            Rall |= bcast64(iR, 31);
            const unsigned accWlo = __reduce_or_sync(0xffffffffu,
                accept ? (unsigned)(1ull << d) : 0u);
            const unsigned accWhi = __reduce_or_sync(0xffffffffu,
                accept ? (unsigned)((1ull << d) >> 32) : 0u);
            Wmem |= ((unsigned long long)accWhi << 32) | accWlo;
            Bm   |= __reduce_or_sync(0xffffffffu, accept ? dres : 0u);
            Sm   |= __reduce_or_sync(0xffffffffu, accept ? sres : 0u);
        }
        // pad unused slots with per-slot scratch rows 64+slot (residues 0..15,
        // mutually conflict-free; weight 0 -> exact no-op)
        if (lane >= members && lane < G) {
            const unsigned off = (64u + (unsigned)lane) * 4u;
            uint2 dm; dm.x = (off << 16) | off; dm.y = 0u;
            g_recs[nch * G + lane] = dm;
        }
        // compact remaining list (program order preserved)
        int wrpos = 0;
        for (int base = 0; base < nrem; base += 32) {
            const int  idx   = base + lane;
            const bool valid = idx < nrem;
            const int  e     = valid ? rlist[idx] : 0;
            const bool keep  = valid && !accf[idx];
            const unsigned kb = __ballot_sync(0xffffffffu, keep);
            if (keep) tmpl[wrpos + __popc(kb & ltmask)] = (short)e;
            wrpos += __popc(kb);
        }
        __syncwarp();
        for (int i = lane; i < wrpos; i += 32) rlist[i] = tmpl[i];
        __syncwarp();
        nrem = wrpos;
        nch++;
    }
    // wrap chunk = copy of chunk 0 (prefetch wrap-around)
    if (lane < G) g_recs[nch * G + lane] = g_recs[lane];
    if (lane == 0) g_nchunks = nch;
}

// ---------------------------------------------------------------------------
// Main kernel: warp = 2 columns x 16 edge slots. Node state [col][row] in
// smem, stride 80 floats (warp halves at bank offset +16; rows 64..79 are
// per-slot scratch for dummies). __syncwarp() orders smem between chunks.
// tanh(x) = 1 - 2/(exp2(x*2log2e)+1) via MUFU ex2/rcp (~1e-6 per-op error).
// ---------------------------------------------------------------------------
__global__ void __launch_bounds__(TB, 1)
net_kernel(const float* __restrict__ x, float* __restrict__ out) {
    __shared__ float vals[CPB * STRIDE];

    const int tid  = threadIdx.x;
    const int lane = tid & 31;
    const int wid  = tid >> 5;
    const int cl   = wid * 2 + (lane >> 4);  // local column 0..7
    const int slot = lane & 15;
    const int bc   = blockIdx.x * CPB;

    for (int i = tid; i < CPB * NINPUT; i += TB) {
        const int r = i >> 3, c = i & 7;
        vals[c * STRIDE + r] = x[r * BATCH + bc + c];
    }
    for (int i = tid; i < CPB * (STRIDE - NINPUT); i += TB) {
        const int r = NINPUT + (i >> 3), c = i & 7;
        vals[c * STRIDE + r] = 0.0f;
    }
    __syncthreads();

    const int nch = g_nchunks;
    char* base = (char*)(vals + cl * STRIDE);

    uint2 rec = __ldg(&g_recs[slot]);
    #pragma unroll 1
    for (int p = 0; p < PASSES; p++) {
        #pragma unroll 2
        for (int c = 0; c < nch; c++) {
            const uint2 nxt = __ldg(&g_recs[(c + 1) * G + slot]);  // wrap=chunk0
            const unsigned sb = rec.x & 0xffffu;
            const unsigned db = rec.x >> 16;
            const float wv = __uint_as_float(rec.y);
            const float v  = *(const float*)(base + sb);
            const float t1 = *(const float*)(base + db) + 1.0f;
            const float a = v * wv;
            float ev;  asm("ex2.approx.f32 %0, %1;" : "=f"(ev) : "f"(a));
            float r2;  asm("rcp.approx.f32 %0, %1;" : "=f"(r2) : "f"(ev + 1.0f));
            *(float*)(base + db) = fmaf(-2.0f, r2, t1);  // pv + 1 - 2/(ev+1)
            rec = nxt;
            __syncwarp();
        }
    }
    __syncthreads();

    for (int i = tid; i < CPB * NOUT; i += TB) {
        const int r = i >> 3, c = i & 7;
        out[r * BATCH + bc + c] = tanhf(vals[c * STRIDE + NINPUT + r]);
    }
}

extern "C" void kernel_launch(void* const* d_in, const int* in_sizes, int n_in,
                              void* d_out, int out_size) {
    const float* x   = (const float*)d_in[0];
    const float* w   = (const float*)d_in[1];
    const int*   src = (const int*)d_in[2];
    const int*   dst = (const int*)d_in[3];
    (void)in_sizes; (void)n_in; (void)out_size;

    sched_kernel<<<1, 32>>>(w, src, dst);
    net_kernel<<<GRIDB, TB>>>(x, (float*)d_out);
}